// round 7
// baseline (speedup 1.0000x reference)
#include <cuda_runtime.h>
#include <cuda_bf16.h>

// Zim_67430986547716 — bbox mask + Gaussian point mask.
// R7: keep R6's u16-SIMD tropical inner loop (min_p(dy2+dx2) via
// __viaddmin_u16x2, exp once at the end). Cut per-block overhead:
//  - grid (256,2) x 512 threads: same 8192 resident warps, half the
//    prologue instances, build loops 2 iters each
//  - fully unrolled 32-point loop: immediate-offset LDS, no loop overhead
// Main loop = 128 issue slots per thread for 4 pixels x 32 points.

#define MASK_N 64
#define NPTS   32
#define INV_STRIDE (1.0f / 16.0f)
#define INV_2SIG2  (1.0f / 882.0f)   // 2*21*21

__global__ __launch_bounds__(512, 3)
void zim_masks_kernel(const float* __restrict__ boxes,
                      const float* __restrict__ pts,
                      float* __restrict__ bbox_out,
                      float* __restrict__ point_out)
{
    __shared__ unsigned int sdx2p[NPTS * 32];  // 4KB: [p][cpair] dx2 u16 pairs, all 64 cols
    __shared__ unsigned int sdy2d[NPTS * 32];  // 4KB: [p][row] (dy2+bias) duplicated u16x2

    const int b      = blockIdx.x;
    const int sub    = blockIdx.y;              // 0 or 1: rows 0-31 / 32-63
    const int i_base = sub << 5;
    const int tid    = threadIdx.x;

    // ---- bbox bounds (uniform; L1 broadcast) ----
    const float x0 = boxes[b * 4 + 0];
    const float y0 = boxes[b * 4 + 1];
    const float x1 = boxes[b * 4 + 2];
    const float y1 = boxes[b * 4 + 3];
    const int xmin_i = max((int)floorf(fminf(x0, x1) * INV_STRIDE), 0);
    const int ymin_i = max((int)floorf(fminf(y0, y1) * INV_STRIDE), 0);
    const int xmax_i = min((int)floorf(fmaxf(x0, x1) * INV_STRIDE) + 1, MASK_N);
    const int ymax_i = min((int)floorf(fmaxf(y0, y1) * INV_STRIDE) + 1, MASK_N);

    // ---- build u16 distance tables (2 iters each, 512 threads) ----
    #pragma unroll
    for (int k = tid; k < NPTS * 32; k += 512) {        // dx2 pairs: all 64 cols
        const int p = k >> 5;
        const float x = __ldg(&pts[(b * NPTS + p) * 2 + 0]);
        const int px = (int)floorf(x * INV_STRIDE);
        const int c0 = (k & 31) << 1;
        const int d0 = c0 - px;
        const int d1 = c0 + 1 - px;
        sdx2p[k] = (unsigned int)(d0 * d0) | ((unsigned int)(d1 * d1) << 16);
    }
    #pragma unroll
    for (int k = tid; k < NPTS * 32; k += 512) {        // dy2+bias duplicated
        const int p = k >> 5;
        const float x = __ldg(&pts[(b * NPTS + p) * 2 + 0]);
        const float y = __ldg(&pts[(b * NPTS + p) * 2 + 1]);
        const int px = (int)floorf(x * INV_STRIDE);
        const int py = (int)floorf(y * INV_STRIDE);
        const bool valid = (px >= 0) & (py >= 0) & (px < MASK_N) & (py < MASK_N);
        const int d = i_base + (k & 31) - py;
        const unsigned int v = (unsigned int)(d * d + (valid ? 0 : 30000));
        sdy2d[k] = v | (v << 16);
    }
    __syncthreads();

    // ---- per-thread: 1 row x 4 cols, fully unrolled u16x2 SIMD min ----
    const int il = tid >> 4;            // 0..31 local row
    const int cg = tid & 15;            // col group: cols 4*cg .. 4*cg+3

    unsigned int m01 = 0xFFFFFFFFu, m23 = 0xFFFFFFFFu;

    const unsigned int* dyp = &sdy2d[il];
    const unsigned int* dxp = &sdx2p[cg * 2];

    #pragma unroll
    for (int p = 0; p < NPTS; p++) {
        const unsigned int dyd = dyp[p * 32];
        const uint2 dx = *reinterpret_cast<const uint2*>(dxp + p * 32);
        m01 = __viaddmin_u16x2(dyd, dx.x, m01);
        m23 = __viaddmin_u16x2(dyd, dx.y, m23);
    }

    // ---- unpack + one exp per pixel ----
    const float g0 = __expf((float)(m01 & 0xFFFFu) * -INV_2SIG2);
    const float g1 = __expf((float)(m01 >> 16)     * -INV_2SIG2);
    const float g2 = __expf((float)(m23 & 0xFFFFu) * -INV_2SIG2);
    const float g3 = __expf((float)(m23 >> 16)     * -INV_2SIG2);

    // ---- stores ----
    const int i = i_base + il;
    const int j = cg << 2;
    const size_t base = (size_t)b * (MASK_N * MASK_N) + (size_t)i * MASK_N + j;

    *reinterpret_cast<float4*>(point_out + base) = make_float4(g0, g1, g2, g3);

    const bool inY = (i >= ymin_i) & (i < ymax_i);
    float4 bv;
    bv.x = (inY & (j + 0 >= xmin_i) & (j + 0 < xmax_i)) ? 1.f : 0.f;
    bv.y = (inY & (j + 1 >= xmin_i) & (j + 1 < xmax_i)) ? 1.f : 0.f;
    bv.z = (inY & (j + 2 >= xmin_i) & (j + 2 < xmax_i)) ? 1.f : 0.f;
    bv.w = (inY & (j + 3 >= xmin_i) & (j + 3 < xmax_i)) ? 1.f : 0.f;
    *reinterpret_cast<float4*>(bbox_out + base) = bv;
}

extern "C" void kernel_launch(void* const* d_in, const int* in_sizes, int n_in,
                              void* d_out, int out_size) {
    const float* boxes = (const float*)d_in[0];   // 256*4
    const float* pts   = (const float*)d_in[1];   // 256*32*2
    float* out = (float*)d_out;                   // 2 * 256*64*64
    const int B = in_sizes[0] / 4;                // 256
    float* bbox_out  = out;
    float* point_out = out + (size_t)B * MASK_N * MASK_N;
    dim3 grid(B, 2);
    zim_masks_kernel<<<grid, 512>>>(boxes, pts, bbox_out, point_out);
}

// round 8
// speedup vs baseline: 1.2059x; 1.2059x over previous
#include <cuda_runtime.h>
#include <cuda_bf16.h>

// Zim_67430986547716 — bbox mask + Gaussian point mask.
// R8: R6 kernel (u16-SIMD tropical min + exp-at-end, 32x32 quadrant blocks,
// unroll 8) with single-wave residency. R6 ran 1024 blocks at 6 blocks/SM max
// -> 888 + 136 two-wave schedule with a 12%-occ tail wave. launch_bounds(256,8)
// makes all 1024 blocks resident in one wave (8/SM x 148 = 1184).

#define MASK_N 64
#define NPTS   32
#define INV_STRIDE (1.0f / 16.0f)
#define INV_2SIG2  (1.0f / 882.0f)   // 2*21*21

__global__ __launch_bounds__(256, 8)
void zim_masks_kernel(const float* __restrict__ boxes,
                      const float* __restrict__ pts,
                      float* __restrict__ bbox_out,
                      float* __restrict__ point_out)
{
    __shared__ unsigned int sdx2p[NPTS * 16];  // 2KB: [p][cpair] = dx2(2c)|dx2(2c+1)<<16
    __shared__ unsigned int sdy2d[NPTS * 32];  // 4KB: [p][row]   = (dy2+bias) duplicated

    const int b      = blockIdx.x;
    const int quad   = blockIdx.y;              // 0..3
    const int i_base = (quad >> 1) << 5;        // 0 or 32
    const int j_base = (quad & 1) << 5;         // 0 or 32
    const int tid    = threadIdx.x;

    // ---- bbox bounds (uniform; L1 broadcast) ----
    const float x0 = boxes[b * 4 + 0];
    const float y0 = boxes[b * 4 + 1];
    const float x1 = boxes[b * 4 + 2];
    const float y1 = boxes[b * 4 + 3];
    const int xmin_i = max((int)floorf(fminf(x0, x1) * INV_STRIDE), 0);
    const int ymin_i = max((int)floorf(fminf(y0, y1) * INV_STRIDE), 0);
    const int xmax_i = min((int)floorf(fmaxf(x0, x1) * INV_STRIDE) + 1, MASK_N);
    const int ymax_i = min((int)floorf(fmaxf(y0, y1) * INV_STRIDE) + 1, MASK_N);

    // ---- build u16 distance tables directly from global pts (L1 broadcast) ----
    #pragma unroll
    for (int k = tid; k < NPTS * 16; k += 256) {        // 2 iters: dx2 pairs
        const int p = k >> 4;
        const float x = __ldg(&pts[(b * NPTS + p) * 2 + 0]);
        const int px = (int)floorf(x * INV_STRIDE);
        const int c0 = j_base + ((k & 15) << 1);
        const int d0 = c0 - px;
        const int d1 = c0 + 1 - px;
        sdx2p[k] = (unsigned int)(d0 * d0) | ((unsigned int)(d1 * d1) << 16);
    }
    #pragma unroll
    for (int k = tid; k < NPTS * 32; k += 256) {        // 4 iters: dy2+bias duplicated
        const int p = k >> 5;
        const float x = __ldg(&pts[(b * NPTS + p) * 2 + 0]);
        const float y = __ldg(&pts[(b * NPTS + p) * 2 + 1]);
        const int px = (int)floorf(x * INV_STRIDE);
        const int py = (int)floorf(y * INV_STRIDE);
        const bool valid = (px >= 0) & (py >= 0) & (px < MASK_N) & (py < MASK_N);
        const int d = i_base + (k & 31) - py;
        const unsigned int v = (unsigned int)(d * d + (valid ? 0 : 30000));
        sdy2d[k] = v | (v << 16);
    }
    __syncthreads();

    // ---- per-thread: 1 row x 4 cols of the quadrant, u16x2 SIMD min ----
    const int il = tid >> 3;            // 0..31 local row
    const int cg = (tid & 7);           // col group: cols 4*cg .. 4*cg+3

    unsigned int m01 = 0xFFFFFFFFu, m23 = 0xFFFFFFFFu;

    const unsigned int* dyp = &sdy2d[il];
    const unsigned int* dxp = &sdx2p[cg * 2];

    #pragma unroll 8
    for (int p = 0; p < NPTS; p++) {
        const unsigned int dyd = dyp[p * 32];
        const uint2 dx = *reinterpret_cast<const uint2*>(dxp + p * 16);
        m01 = __viaddmin_u16x2(dyd, dx.x, m01);
        m23 = __viaddmin_u16x2(dyd, dx.y, m23);
    }

    // ---- unpack + one exp per pixel ----
    const float g0 = __expf((float)(m01 & 0xFFFFu) * -INV_2SIG2);
    const float g1 = __expf((float)(m01 >> 16)     * -INV_2SIG2);
    const float g2 = __expf((float)(m23 & 0xFFFFu) * -INV_2SIG2);
    const float g3 = __expf((float)(m23 >> 16)     * -INV_2SIG2);

    // ---- stores ----
    const int i = i_base + il;
    const int j = j_base + (cg << 2);
    const size_t base = (size_t)b * (MASK_N * MASK_N) + (size_t)i * MASK_N + j;

    *reinterpret_cast<float4*>(point_out + base) = make_float4(g0, g1, g2, g3);

    const bool inY = (i >= ymin_i) & (i < ymax_i);
    float4 bv;
    bv.x = (inY & (j + 0 >= xmin_i) & (j + 0 < xmax_i)) ? 1.f : 0.f;
    bv.y = (inY & (j + 1 >= xmin_i) & (j + 1 < xmax_i)) ? 1.f : 0.f;
    bv.z = (inY & (j + 2 >= xmin_i) & (j + 2 < xmax_i)) ? 1.f : 0.f;
    bv.w = (inY & (j + 3 >= xmin_i) & (j + 3 < xmax_i)) ? 1.f : 0.f;
    *reinterpret_cast<float4*>(bbox_out + base) = bv;
}

extern "C" void kernel_launch(void* const* d_in, const int* in_sizes, int n_in,
                              void* d_out, int out_size) {
    const float* boxes = (const float*)d_in[0];   // 256*4
    const float* pts   = (const float*)d_in[1];   // 256*32*2
    float* out = (float*)d_out;                   // 2 * 256*64*64
    const int B = in_sizes[0] / 4;                // 256
    float* bbox_out  = out;
    float* point_out = out + (size_t)B * MASK_N * MASK_N;
    dim3 grid(B, 4);
    zim_masks_kernel<<<grid, 256>>>(boxes, pts, bbox_out, point_out);
}